// round 7
// baseline (speedup 1.0000x reference)
#include <cuda_runtime.h>
#include <cstdint>
#include <cstddef>

// Fixed shapes: n=512, H=512, B=256
#define BB 256
#define HH 512
#define NN 512
#define GBLK 128      // persistent blocks (<= SM count; all co-resident)
#define NTHR 256
#define NEG_INF (-1.0e9f)
#define F32_TINY 1.17549435e-38f

// -------- device scratch (no allocations allowed) --------
__device__ float    g_h0[2][BB * HH];
__device__ float    g_h1[2][BB * HH];
__device__ float    g_logits[BB * NN];
__device__ int      g_sel[BB];
__device__ unsigned g_avail[BB * (NN / 32)];
__device__ float    g_lp[BB];
__device__ float    g_rowsum[3 * HH];
__device__ unsigned g_bar_cnt;   // zero-init at module load; self-restoring
__device__ unsigned g_bar_gen;

// -------- Threefry-2x32 (20 rounds), bit-exact JAX replica --------
__device__ __forceinline__ unsigned rotl32(unsigned v, int r) {
    return (v << r) | (v >> (32 - r));
}

__device__ __forceinline__ void tf2x32(unsigned ks0, unsigned ks1,
                                       unsigned x0, unsigned x1,
                                       unsigned& o0, unsigned& o1)
{
    unsigned ks2 = ks0 ^ ks1 ^ 0x1BD11BDAu;
    x0 += ks0; x1 += ks1;
#define TF_R4(a,b,c,d) \
    x0 += x1; x1 = rotl32(x1,(a)); x1 ^= x0; \
    x0 += x1; x1 = rotl32(x1,(b)); x1 ^= x0; \
    x0 += x1; x1 = rotl32(x1,(c)); x1 ^= x0; \
    x0 += x1; x1 = rotl32(x1,(d)); x1 ^= x0;
    TF_R4(13,15,26,6)   x0 += ks1; x1 += ks2 + 1u;
    TF_R4(17,29,16,24)  x0 += ks2; x1 += ks0 + 2u;
    TF_R4(13,15,26,6)   x0 += ks0; x1 += ks1 + 3u;
    TF_R4(17,29,16,24)  x0 += ks1; x1 += ks2 + 4u;
    TF_R4(13,15,26,6)   x0 += ks2; x1 += ks0 + 5u;
#undef TF_R4
    o0 = x0; o1 = x1;
}

// XLA lowers logistic(x) as 0.5 + 0.5*tanh(0.5*x); mirror that op graph.
__device__ __forceinline__ float jax_sigmoid(float x) {
    return __fadd_rn(0.5f, __fmul_rn(0.5f, tanhf(__fmul_rn(0.5f, x))));
}

// L2-coherent float4 load (persistent kernel: L1 may hold stale lines)
__device__ __forceinline__ float4 ldcg4(const float* p) {
    return __ldcg(reinterpret_cast<const float4*>(p));
}

// -------- software grid barrier (all GBLK blocks resident) --------
__device__ __forceinline__ void gsync() {
    __syncthreads();
    if (threadIdx.x == 0) {
        __threadfence();                               // publish my writes
        unsigned gen = *(volatile unsigned*)&g_bar_gen;
        if (atomicAdd(&g_bar_cnt, 1u) == GBLK - 1u) {
            atomicExch(&g_bar_cnt, 0u);
            __threadfence();
            atomicAdd(&g_bar_gen, 1u);                 // release
        } else {
            while (*(volatile unsigned*)&g_bar_gen == gen) { }
        }
        __threadfence();
    }
    __syncthreads();
}

__global__ void __launch_bounds__(NTHR, 1) perm_persistent(
    const float* __restrict__ Wih0, const float* __restrict__ Whh0,
    const float* __restrict__ bih0, const float* __restrict__ bhh0,
    const float* __restrict__ Wih1, const float* __restrict__ Whh1,
    const float* __restrict__ bih1, const float* __restrict__ bhh1,
    const float* __restrict__ Wout, const float* __restrict__ bout,
    float* __restrict__ out)
{
    __shared__ float SM[8][32][33];   // union across phases (33.8 KB)

    const int blk = blockIdx.x;
    const int tid = threadIdx.x;

    // ---------------- init (per-launch state reset) ----------------
    {
        for (int i = blk * NTHR + tid; i < BB * HH; i += GBLK * NTHR) {
            g_h0[0][i] = 0.0f;
            g_h1[0][i] = 0.0f;
        }
        // block-private per-row state: block owns batch rows 2*blk, 2*blk+1
        if (tid < 2) g_lp[2 * blk + tid] = 0.0f;
        if (tid < 32) g_avail[(2 * blk + (tid >> 4)) * (NN / 32) + (tid & 15)] = 0xFFFFFFFFu;
        // rowsum(W_ih0): gi at t=0 (x = ones). One warp per row, fixed order.
        int lane = tid & 31;
        for (int row = blk * 8 + (tid >> 5); row < 3 * HH; row += GBLK * 8) {
            const float* rp = Wih0 + (size_t)row * HH;
            float s = 0.0f;
            for (int k = lane; k < HH; k += 32) s = __fadd_rn(s, rp[k]);
#pragma unroll
            for (int off = 16; off > 0; off >>= 1)
                s = __fadd_rn(s, __shfl_xor_sync(0xFFFFFFFFu, s, off));
            if (lane == 0) g_rowsum[row] = s;
        }
    }
    gsync();

    // tile job mapping: 8 batch tiles x 16 hidden tiles == GBLK jobs exactly
    const int jx = blk & 15;         // hidden tile
    const int jy = blk >> 4;         // batch tile
    const int bm0 = jy * 32;
    const int jn0 = jx * 32;
    const int tx = tid & 15, ty = tid >> 4;
    const int lr = tid >> 3, lc = (tid & 7) << 2;

    for (int t = 0; t < NN; t++) {
        const int p = t & 1;
        const float* h0_in  = g_h0[p];
        float*       h0_out = g_h0[p ^ 1];
        const float* h1_in  = g_h1[p];
        float*       h1_out = g_h1[p ^ 1];

        // ---------------- layer 0: h0n = GRU(onehot(sel), h0) ----------------
        {
            float acc[3][2][2] = {};
            float4 pa  = ldcg4(h0_in + (size_t)(bm0 + lr) * HH + lc);
            float4 pb0 = *reinterpret_cast<const float4*>(Whh0 + (size_t)(jn0 + lr) * HH + lc);
            float4 pb1 = *reinterpret_cast<const float4*>(Whh0 + (size_t)(HH + jn0 + lr) * HH + lc);
            float4 pb2 = *reinterpret_cast<const float4*>(Whh0 + (size_t)(2 * HH + jn0 + lr) * HH + lc);
            for (int k0 = 0; k0 < HH; k0 += 32) {
                SM[0][lr][lc] = pa.x;  SM[0][lr][lc+1] = pa.y;  SM[0][lr][lc+2] = pa.z;  SM[0][lr][lc+3] = pa.w;
                SM[1][lr][lc] = pb0.x; SM[1][lr][lc+1] = pb0.y; SM[1][lr][lc+2] = pb0.z; SM[1][lr][lc+3] = pb0.w;
                SM[2][lr][lc] = pb1.x; SM[2][lr][lc+1] = pb1.y; SM[2][lr][lc+2] = pb1.z; SM[2][lr][lc+3] = pb1.w;
                SM[3][lr][lc] = pb2.x; SM[3][lr][lc+1] = pb2.y; SM[3][lr][lc+2] = pb2.z; SM[3][lr][lc+3] = pb2.w;
                __syncthreads();
                if (k0 + 32 < HH) {     // prefetch next k-tile under the compute
                    int kn = k0 + 32;
                    pa  = ldcg4(h0_in + (size_t)(bm0 + lr) * HH + kn + lc);
                    pb0 = *reinterpret_cast<const float4*>(Whh0 + (size_t)(jn0 + lr) * HH + kn + lc);
                    pb1 = *reinterpret_cast<const float4*>(Whh0 + (size_t)(HH + jn0 + lr) * HH + kn + lc);
                    pb2 = *reinterpret_cast<const float4*>(Whh0 + (size_t)(2 * HH + jn0 + lr) * HH + kn + lc);
                }
#pragma unroll
                for (int k = 0; k < 32; k++) {
                    float a0 = SM[0][2*ty][k], a1 = SM[0][2*ty+1][k];
                    {
                        float b0 = SM[1][2*tx][k], b1 = SM[1][2*tx+1][k];
                        acc[0][0][0] = fmaf(a0, b0, acc[0][0][0]);
                        acc[0][0][1] = fmaf(a0, b1, acc[0][0][1]);
                        acc[0][1][0] = fmaf(a1, b0, acc[0][1][0]);
                        acc[0][1][1] = fmaf(a1, b1, acc[0][1][1]);
                    }
                    {
                        float b0 = SM[2][2*tx][k], b1 = SM[2][2*tx+1][k];
                        acc[1][0][0] = fmaf(a0, b0, acc[1][0][0]);
                        acc[1][0][1] = fmaf(a0, b1, acc[1][0][1]);
                        acc[1][1][0] = fmaf(a1, b0, acc[1][1][0]);
                        acc[1][1][1] = fmaf(a1, b1, acc[1][1][1]);
                    }
                    {
                        float b0 = SM[3][2*tx][k], b1 = SM[3][2*tx+1][k];
                        acc[2][0][0] = fmaf(a0, b0, acc[2][0][0]);
                        acc[2][0][1] = fmaf(a0, b1, acc[2][0][1]);
                        acc[2][1][0] = fmaf(a1, b0, acc[2][1][0]);
                        acc[2][1][1] = fmaf(a1, b1, acc[2][1][1]);
                    }
                }
                __syncthreads();
            }
#pragma unroll
            for (int mi = 0; mi < 2; mi++) {
                int b = bm0 + 2*ty + mi;
                int xsel = (t > 0) ? __ldcg(&g_sel[b]) : 0;
#pragma unroll
                for (int ni = 0; ni < 2; ni++) {
                    int j = jn0 + 2*tx + ni;
                    float ir, iz, inn;
                    if (t == 0) {
                        ir  = __ldcg(&g_rowsum[j]);
                        iz  = __ldcg(&g_rowsum[j + HH]);
                        inn = __ldcg(&g_rowsum[j + 2*HH]);
                    } else {
                        ir  = Wih0[(size_t)j * HH + xsel];
                        iz  = Wih0[(size_t)(j + HH) * HH + xsel];
                        inn = Wih0[(size_t)(j + 2*HH) * HH + xsel];
                    }
                    ir  = __fadd_rn(ir,  bih0[j]);
                    iz  = __fadd_rn(iz,  bih0[j + HH]);
                    inn = __fadd_rn(inn, bih0[j + 2*HH]);
                    float hr = __fadd_rn(acc[0][mi][ni], bhh0[j]);
                    float hz = __fadd_rn(acc[1][mi][ni], bhh0[j + HH]);
                    float hn = __fadd_rn(acc[2][mi][ni], bhh0[j + 2*HH]);
                    float r  = jax_sigmoid(__fadd_rn(ir, hr));
                    float z  = jax_sigmoid(__fadd_rn(iz, hz));
                    float ng = tanhf(__fadd_rn(inn, __fmul_rn(r, hn)));
                    float hp = __ldcg(&h0_in[(size_t)b * HH + j]);
                    h0_out[(size_t)b * HH + j] =
                        __fadd_rn(__fmul_rn(__fsub_rn(1.0f, z), ng), __fmul_rn(z, hp));
                }
            }
        }
        gsync();

        // ---------------- layer 1: h1n = GRU(h0n, h1) ----------------
        {
            float acc[6][2][2] = {};
            float4 pa0 = ldcg4(h0_out + (size_t)(bm0 + lr) * HH + lc);
            float4 pa1 = ldcg4(h1_in  + (size_t)(bm0 + lr) * HH + lc);
            float4 pw[6];
#pragma unroll
            for (int g = 0; g < 3; g++) {
                pw[g]   = *reinterpret_cast<const float4*>(Wih1 + (size_t)(g * HH + jn0 + lr) * HH + lc);
                pw[3+g] = *reinterpret_cast<const float4*>(Whh1 + (size_t)(g * HH + jn0 + lr) * HH + lc);
            }
            for (int k0 = 0; k0 < HH; k0 += 32) {
                SM[0][lr][lc] = pa0.x; SM[0][lr][lc+1] = pa0.y; SM[0][lr][lc+2] = pa0.z; SM[0][lr][lc+3] = pa0.w;
                SM[1][lr][lc] = pa1.x; SM[1][lr][lc+1] = pa1.y; SM[1][lr][lc+2] = pa1.z; SM[1][lr][lc+3] = pa1.w;
#pragma unroll
                for (int g = 0; g < 6; g++) {
                    SM[2+g][lr][lc]   = pw[g].x; SM[2+g][lr][lc+1] = pw[g].y;
                    SM[2+g][lr][lc+2] = pw[g].z; SM[2+g][lr][lc+3] = pw[g].w;
                }
                __syncthreads();
                if (k0 + 32 < HH) {
                    int kn = k0 + 32;
                    pa0 = ldcg4(h0_out + (size_t)(bm0 + lr) * HH + kn + lc);
                    pa1 = ldcg4(h1_in  + (size_t)(bm0 + lr) * HH + kn + lc);
#pragma unroll
                    for (int g = 0; g < 3; g++) {
                        pw[g]   = *reinterpret_cast<const float4*>(Wih1 + (size_t)(g * HH + jn0 + lr) * HH + kn + lc);
                        pw[3+g] = *reinterpret_cast<const float4*>(Whh1 + (size_t)(g * HH + jn0 + lr) * HH + kn + lc);
                    }
                }
#pragma unroll
                for (int k = 0; k < 32; k++) {
                    float x0 = SM[0][2*ty][k], x1 = SM[0][2*ty+1][k];
                    float h0 = SM[1][2*ty][k], h1 = SM[1][2*ty+1][k];
#pragma unroll
                    for (int g = 0; g < 3; g++) {
                        float b0 = SM[2+g][2*tx][k], b1 = SM[2+g][2*tx+1][k];
                        acc[g][0][0] = fmaf(x0, b0, acc[g][0][0]);
                        acc[g][0][1] = fmaf(x0, b1, acc[g][0][1]);
                        acc[g][1][0] = fmaf(x1, b0, acc[g][1][0]);
                        acc[g][1][1] = fmaf(x1, b1, acc[g][1][1]);
                        float c0 = SM[5+g][2*tx][k], c1 = SM[5+g][2*tx+1][k];
                        acc[3+g][0][0] = fmaf(h0, c0, acc[3+g][0][0]);
                        acc[3+g][0][1] = fmaf(h0, c1, acc[3+g][0][1]);
                        acc[3+g][1][0] = fmaf(h1, c0, acc[3+g][1][0]);
                        acc[3+g][1][1] = fmaf(h1, c1, acc[3+g][1][1]);
                    }
                }
                __syncthreads();
            }
#pragma unroll
            for (int mi = 0; mi < 2; mi++) {
#pragma unroll
                for (int ni = 0; ni < 2; ni++) {
                    int b = bm0 + 2*ty + mi;
                    int j = jn0 + 2*tx + ni;
                    float ir  = __fadd_rn(acc[0][mi][ni], bih1[j]);
                    float iz  = __fadd_rn(acc[1][mi][ni], bih1[j + HH]);
                    float inn = __fadd_rn(acc[2][mi][ni], bih1[j + 2*HH]);
                    float hr  = __fadd_rn(acc[3][mi][ni], bhh1[j]);
                    float hz  = __fadd_rn(acc[4][mi][ni], bhh1[j + HH]);
                    float hn  = __fadd_rn(acc[5][mi][ni], bhh1[j + 2*HH]);
                    float r  = jax_sigmoid(__fadd_rn(ir, hr));
                    float z  = jax_sigmoid(__fadd_rn(iz, hz));
                    float ng = tanhf(__fadd_rn(inn, __fmul_rn(r, hn)));
                    float hp = __ldcg(&h1_in[(size_t)b * HH + j]);
                    h1_out[(size_t)b * HH + j] =
                        __fadd_rn(__fmul_rn(__fsub_rn(1.0f, z), ng), __fmul_rn(z, hp));
                }
            }
        }
        gsync();

        // ---------------- logits = h1n @ W_out^T + b_out ----------------
        {
            float acc[2][2] = {};
            float4 pa = ldcg4(h1_out + (size_t)(bm0 + lr) * HH + lc);
            float4 pb = *reinterpret_cast<const float4*>(Wout + (size_t)(jn0 + lr) * HH + lc);
            for (int k0 = 0; k0 < HH; k0 += 32) {
                SM[0][lr][lc] = pa.x; SM[0][lr][lc+1] = pa.y; SM[0][lr][lc+2] = pa.z; SM[0][lr][lc+3] = pa.w;
                SM[1][lr][lc] = pb.x; SM[1][lr][lc+1] = pb.y; SM[1][lr][lc+2] = pb.z; SM[1][lr][lc+3] = pb.w;
                __syncthreads();
                if (k0 + 32 < HH) {
                    int kn = k0 + 32;
                    pa = ldcg4(h1_out + (size_t)(bm0 + lr) * HH + kn + lc);
                    pb = *reinterpret_cast<const float4*>(Wout + (size_t)(jn0 + lr) * HH + kn + lc);
                }
#pragma unroll
                for (int k = 0; k < 32; k++) {
                    float a0 = SM[0][2*ty][k], a1 = SM[0][2*ty+1][k];
                    float b0 = SM[1][2*tx][k], b1 = SM[1][2*tx+1][k];
                    acc[0][0] = fmaf(a0, b0, acc[0][0]);
                    acc[0][1] = fmaf(a0, b1, acc[0][1]);
                    acc[1][0] = fmaf(a1, b0, acc[1][0]);
                    acc[1][1] = fmaf(a1, b1, acc[1][1]);
                }
                __syncthreads();
            }
#pragma unroll
            for (int mi = 0; mi < 2; mi++)
#pragma unroll
                for (int ni = 0; ni < 2; ni++) {
                    int b = bm0 + 2*ty + mi;
                    int c = jn0 + 2*tx + ni;
                    g_logits[(size_t)b * NN + c] = __fadd_rn(acc[mi][ni], bout[c]);
                }
        }
        gsync();

        // ---------------- sample (block owns rows 2*blk, 2*blk+1) ----------------
        {
            float* sv  = &SM[0][0][0];
            int*   si  = reinterpret_cast<int*>(&SM[1][0][0]);
            float* vv  = &SM[2][0][0];
            float* red = &SM[4][0][0];

            unsigned sk0, sk1;
            tf2x32(0u, 42u, 0u, (unsigned)t, sk0, sk1);   // step key

            for (int rr = 0; rr < 2; rr++) {
                int b = 2 * blk + rr;
                int c = tid;                  // handles columns c and c+256

                float lg0 = __ldcg(&g_logits[(size_t)b * NN + c]);
                float lg1 = __ldcg(&g_logits[(size_t)b * NN + c + 256]);
                unsigned w0 = g_avail[b * (NN/32) + (c >> 5)];
                unsigned w1 = g_avail[b * (NN/32) + (c >> 5) + 8];
                float v0 = ((w0 >> (c & 31)) & 1u) ? lg0 : NEG_INF;
                float v1 = ((w1 >> (c & 31)) & 1u) ? lg1 : NEG_INF;

                unsigned o0, o1, bits;
                tf2x32(sk0, sk1, 0u, (unsigned)(b * NN + c), o0, o1);
                bits = o0 ^ o1;
                float f0 = __fsub_rn(__uint_as_float((bits >> 9) | 0x3F800000u), 1.0f);
                float g0 = -logf(-logf(fmaxf(f0, F32_TINY)));
                tf2x32(sk0, sk1, 0u, (unsigned)(b * NN + c + 256), o0, o1);
                bits = o0 ^ o1;
                float f1 = __fsub_rn(__uint_as_float((bits >> 9) | 0x3F800000u), 1.0f);
                float g1 = -logf(-logf(fmaxf(f1, F32_TINY)));

                float s0 = __fadd_rn(g0, v0);
                float s1 = __fadd_rn(g1, v1);
                float smax; int imax;
                if (s1 > s0) { smax = s1; imax = c + 256; } else { smax = s0; imax = c; }

                sv[c] = smax; si[c] = imax;
                vv[c] = v0;  vv[c + 256] = v1;
                red[c] = fmaxf(v0, v1);
                __syncthreads();

                for (int off = 128; off > 0; off >>= 1) {
                    if (c < off) {
                        float o  = sv[c + off];
                        int   oi = si[c + off];
                        if (o > sv[c] || (o == sv[c] && oi < si[c])) { sv[c] = o; si[c] = oi; }
                        red[c] = fmaxf(red[c], red[c + off]);
                    }
                    __syncthreads();
                }
                int   idx  = si[0];
                float vmax = red[0];
                __syncthreads();

                red[c] = __fadd_rn(expf(__fsub_rn(v0, vmax)), expf(__fsub_rn(v1, vmax)));
                __syncthreads();
                for (int off = 128; off > 0; off >>= 1) {
                    if (c < off) red[c] = __fadd_rn(red[c], red[c + off]);
                    __syncthreads();
                }

                if (c == 0) {
                    float S  = red[0];
                    float ps = __fdiv_rn(expf(__fsub_rn(vv[idx], vmax)), S);
                    float lp = __fadd_rn(g_lp[b], logf(__fadd_rn(ps, 1e-9f)));
                    g_lp[b]  = lp;
                    g_sel[b] = idx;
                    g_avail[b * (NN/32) + (idx >> 5)] &= ~(1u << (idx & 31));
                    out[(size_t)b * NN * NN + (size_t)t * NN + idx] = 1.0f;
                    if (t == NN - 1) out[(size_t)BB * NN * NN + b] = lp;
                }
                __syncthreads();
            }
        }
        gsync();
    }
}

// -------- host launcher: 2 graph nodes (memset + persistent kernel) --------
extern "C" void kernel_launch(void* const* d_in, const int* in_sizes, int n_in,
                              void* d_out, int out_size)
{
    int base = (n_in == 11) ? 1 : 0;   // batch_size scalar first per metadata
    const float* Wih0 = (const float*)d_in[base + 0];
    const float* Whh0 = (const float*)d_in[base + 1];
    const float* bih0 = (const float*)d_in[base + 2];
    const float* bhh0 = (const float*)d_in[base + 3];
    const float* Wih1 = (const float*)d_in[base + 4];
    const float* Whh1 = (const float*)d_in[base + 5];
    const float* bih1 = (const float*)d_in[base + 6];
    const float* bhh1 = (const float*)d_in[base + 7];
    const float* Wout = (const float*)d_in[base + 8];
    const float* bout = (const float*)d_in[base + 9];
    float* out = (float*)d_out;
    (void)in_sizes;

    cudaMemsetAsync(d_out, 0, (size_t)out_size * sizeof(float), 0);
    perm_persistent<<<GBLK, NTHR>>>(Wih0, Whh0, bih0, bhh0,
                                    Wih1, Whh1, bih1, bhh1,
                                    Wout, bout, out);
}

// round 8
// speedup vs baseline: 1.0172x; 1.0172x over previous
#include <cuda_runtime.h>
#include <cstdint>
#include <cstddef>

// Fixed shapes: n=512, H=512, B=256
#define BB 256
#define HH 512
#define NN 512
#define GBLK 128      // persistent blocks (all co-resident; 8x16 tile jobs)
#define NTHR 256
#define TS 34         // smem row stride (even -> LDS.64 aligned)
#define NEG_INF (-1.0e9f)
#define F32_TINY 1.17549435e-38f

// -------- device scratch (no allocations allowed) --------
__device__ float    g_h0[2][BB * HH];
__device__ float    g_h1[2][BB * HH];
__device__ float    g_logits[BB * NN];
__device__ int      g_sel[BB];
__device__ unsigned g_avail[BB * (NN / 32)];
__device__ float    g_lp[BB];
__device__ float    g_rowsum[3 * HH];
__device__ unsigned g_bar_cnt;   // zero-init; self-restoring
__device__ unsigned g_bar_gen;

// -------- Threefry-2x32 (20 rounds), bit-exact JAX replica --------
__device__ __forceinline__ unsigned rotl32(unsigned v, int r) {
    return (v << r) | (v >> (32 - r));
}

__device__ __forceinline__ void tf2x32(unsigned ks0, unsigned ks1,
                                       unsigned x0, unsigned x1,
                                       unsigned& o0, unsigned& o1)
{
    unsigned ks2 = ks0 ^ ks1 ^ 0x1BD11BDAu;
    x0 += ks0; x1 += ks1;
#define TF_R4(a,b,c,d) \
    x0 += x1; x1 = rotl32(x1,(a)); x1 ^= x0; \
    x0 += x1; x1 = rotl32(x1,(b)); x1 ^= x0; \
    x0 += x1; x1 = rotl32(x1,(c)); x1 ^= x0; \
    x0 += x1; x1 = rotl32(x1,(d)); x1 ^= x0;
    TF_R4(13,15,26,6)   x0 += ks1; x1 += ks2 + 1u;
    TF_R4(17,29,16,24)  x0 += ks2; x1 += ks0 + 2u;
    TF_R4(13,15,26,6)   x0 += ks0; x1 += ks1 + 3u;
    TF_R4(17,29,16,24)  x0 += ks1; x1 += ks2 + 4u;
    TF_R4(13,15,26,6)   x0 += ks2; x1 += ks0 + 5u;
#undef TF_R4
    o0 = x0; o1 = x1;
}

// XLA lowers logistic(x) as 0.5 + 0.5*tanh(0.5*x); mirror that op graph.
__device__ __forceinline__ float jax_sigmoid(float x) {
    return __fadd_rn(0.5f, __fmul_rn(0.5f, tanhf(__fmul_rn(0.5f, x))));
}

// L2-coherent float4 load (persistent kernel: L1 may hold stale lines)
__device__ __forceinline__ float4 ldcg4(const float* p) {
    return __ldcg(reinterpret_cast<const float4*>(p));
}

// -------- packed f32x2 FMA: two IEEE fp32 FMAs per instruction --------
union f2u { float2 f; unsigned long long u; };

__device__ __forceinline__ float2 ffma2(float2 a, float2 b, float2 c) {
    f2u A, B, C, D;
    A.f = a; B.f = b; C.f = c;
    asm("fma.rn.f32x2 %0, %1, %2, %3;" : "=l"(D.u) : "l"(A.u), "l"(B.u), "l"(C.u));
    return D.f;
}
__device__ __forceinline__ float2 bc2(float a) { return make_float2(a, a); }

// transposed smem store of a k-direction float4
__device__ __forceinline__ void st_tr(float* buf, int lc, int lr, float4 v) {
    buf[(lc + 0) * TS + lr] = v.x;
    buf[(lc + 1) * TS + lr] = v.y;
    buf[(lc + 2) * TS + lr] = v.z;
    buf[(lc + 3) * TS + lr] = v.w;
}

__device__ __forceinline__ float2 lds2(const float* p) {
    return *reinterpret_cast<const float2*>(p);
}

// -------- software grid barrier (all GBLK blocks resident) --------
__device__ __forceinline__ void gsync() {
    __syncthreads();
    if (threadIdx.x == 0) {
        __threadfence();
        unsigned gen = *(volatile unsigned*)&g_bar_gen;
        if (atomicAdd(&g_bar_cnt, 1u) == GBLK - 1u) {
            atomicExch(&g_bar_cnt, 0u);
            __threadfence();
            atomicAdd(&g_bar_gen, 1u);
        } else {
            while (*(volatile unsigned*)&g_bar_gen == gen) { }
        }
        __threadfence();
    }
    __syncthreads();
}

#define SMBUF(i) (SM + (i) * (32 * TS))

__global__ void __launch_bounds__(NTHR, 1) perm_persistent(
    const float* __restrict__ Wih0, const float* __restrict__ Whh0,
    const float* __restrict__ bih0, const float* __restrict__ bhh0,
    const float* __restrict__ Wih1, const float* __restrict__ Whh1,
    const float* __restrict__ bih1, const float* __restrict__ bhh1,
    const float* __restrict__ Wout, const float* __restrict__ bout,
    float* __restrict__ out)
{
    __shared__ float SM[8 * 32 * TS];   // 34.8 KB, unioned across phases

    const int blk = blockIdx.x;
    const int tid = threadIdx.x;

    // ---------------- init (per-launch state reset) ----------------
    {
        for (int i = blk * NTHR + tid; i < BB * HH; i += GBLK * NTHR) {
            g_h0[0][i] = 0.0f;
            g_h1[0][i] = 0.0f;
        }
        if (tid < 2) g_lp[2 * blk + tid] = 0.0f;
        if (tid < 32) g_avail[(2 * blk + (tid >> 4)) * (NN / 32) + (tid & 15)] = 0xFFFFFFFFu;
        int lane = tid & 31;
        for (int row = blk * 8 + (tid >> 5); row < 3 * HH; row += GBLK * 8) {
            const float* rp = Wih0 + (size_t)row * HH;
            float s = 0.0f;
            for (int k = lane; k < HH; k += 32) s = __fadd_rn(s, rp[k]);
#pragma unroll
            for (int off = 16; off > 0; off >>= 1)
                s = __fadd_rn(s, __shfl_xor_sync(0xFFFFFFFFu, s, off));
            if (lane == 0) g_rowsum[row] = s;
        }
    }
    gsync();

    // tile jobs: 8 batch tiles x 16 hidden tiles == GBLK
    const int jx = blk & 15;
    const int jy = blk >> 4;
    const int bm0 = jy * 32;
    const int jn0 = jx * 32;
    const int tx = tid & 15, ty = tid >> 4;
    const int lr = tid >> 3, lc = (tid & 7) << 2;

    for (int t = 0; t < NN; t++) {
        const int p = t & 1;
        const float* h0_in  = g_h0[p];
        float*       h0_out = g_h0[p ^ 1];
        const float* h1_in  = g_h1[p];
        float*       h1_out = g_h1[p ^ 1];

        // ---------------- layer 0: h0n = GRU(onehot(sel), h0) ----------------
        {
            // hoisted input-gate gather (overlaps with the GEMM below)
            float gi[2][3][2];
            if (t == 0) {
#pragma unroll
                for (int ni = 0; ni < 2; ni++) {
                    int j = jn0 + 2 * tx + ni;
                    float r0 = __ldcg(&g_rowsum[j]);
                    float r1 = __ldcg(&g_rowsum[j + HH]);
                    float r2 = __ldcg(&g_rowsum[j + 2 * HH]);
#pragma unroll
                    for (int mi = 0; mi < 2; mi++) {
                        gi[mi][0][ni] = r0; gi[mi][1][ni] = r1; gi[mi][2][ni] = r2;
                    }
                }
            } else {
#pragma unroll
                for (int mi = 0; mi < 2; mi++) {
                    int xs = __ldcg(&g_sel[bm0 + 2 * ty + mi]);
#pragma unroll
                    for (int g = 0; g < 3; g++)
#pragma unroll
                        for (int ni = 0; ni < 2; ni++)
                            gi[mi][g][ni] = __ldg(&Wih0[(size_t)(g * HH + jn0 + 2 * tx + ni) * HH + xs]);
                }
            }

            float2 acc[3][2];   // [gate][mi], lanes = ni
#pragma unroll
            for (int g = 0; g < 3; g++) { acc[g][0] = make_float2(0.f, 0.f); acc[g][1] = make_float2(0.f, 0.f); }

            float4 pa  = ldcg4(h0_in + (size_t)(bm0 + lr) * HH + lc);
            float4 pb0 = *reinterpret_cast<const float4*>(Whh0 + (size_t)(jn0 + lr) * HH + lc);
            float4 pb1 = *reinterpret_cast<const float4*>(Whh0 + (size_t)(HH + jn0 + lr) * HH + lc);
            float4 pb2 = *reinterpret_cast<const float4*>(Whh0 + (size_t)(2 * HH + jn0 + lr) * HH + lc);
#pragma unroll 1
            for (int k0 = 0; k0 < HH; k0 += 32) {
                st_tr(SMBUF(0), lc, lr, pa);
                st_tr(SMBUF(1), lc, lr, pb0);
                st_tr(SMBUF(2), lc, lr, pb1);
                st_tr(SMBUF(3), lc, lr, pb2);
                __syncthreads();
                if (k0 + 32 < HH) {
                    int kn = k0 + 32;
                    pa  = ldcg4(h0_in + (size_t)(bm0 + lr) * HH + kn + lc);
                    pb0 = *reinterpret_cast<const float4*>(Whh0 + (size_t)(jn0 + lr) * HH + kn + lc);
                    pb1 = *reinterpret_cast<const float4*>(Whh0 + (size_t)(HH + jn0 + lr) * HH + kn + lc);
                    pb2 = *reinterpret_cast<const float4*>(Whh0 + (size_t)(2 * HH + jn0 + lr) * HH + kn + lc);
                }
#pragma unroll
                for (int k = 0; k < 32; k++) {
                    float2 av = lds2(SMBUF(0) + k * TS + 2 * ty);
                    float2 a0 = bc2(av.x), a1 = bc2(av.y);
#pragma unroll
                    for (int g = 0; g < 3; g++) {
                        float2 bw = lds2(SMBUF(1 + g) + k * TS + 2 * tx);
                        acc[g][0] = ffma2(a0, bw, acc[g][0]);
                        acc[g][1] = ffma2(a1, bw, acc[g][1]);
                    }
                }
                __syncthreads();
            }
#pragma unroll
            for (int mi = 0; mi < 2; mi++) {
                int b = bm0 + 2 * ty + mi;
#pragma unroll
                for (int ni = 0; ni < 2; ni++) {
                    int j = jn0 + 2 * tx + ni;
                    float ir  = __fadd_rn(gi[mi][0][ni], bih0[j]);
                    float iz  = __fadd_rn(gi[mi][1][ni], bih0[j + HH]);
                    float inn = __fadd_rn(gi[mi][2][ni], bih0[j + 2 * HH]);
                    float hr = __fadd_rn(ni ? acc[0][mi].y : acc[0][mi].x, bhh0[j]);
                    float hz = __fadd_rn(ni ? acc[1][mi].y : acc[1][mi].x, bhh0[j + HH]);
                    float hn = __fadd_rn(ni ? acc[2][mi].y : acc[2][mi].x, bhh0[j + 2 * HH]);
                    float r  = jax_sigmoid(__fadd_rn(ir, hr));
                    float z  = jax_sigmoid(__fadd_rn(iz, hz));
                    float ng = tanhf(__fadd_rn(inn, __fmul_rn(r, hn)));
                    float hp = __ldcg(&h0_in[(size_t)b * HH + j]);
                    h0_out[(size_t)b * HH + j] =
                        __fadd_rn(__fmul_rn(__fsub_rn(1.0f, z), ng), __fmul_rn(z, hp));
                }
            }
        }
        gsync();

        // ---------------- layer 1: h1n = GRU(h0n, h1) ----------------
        {
            float2 accI[3][2], accH[3][2];
#pragma unroll
            for (int g = 0; g < 3; g++) {
                accI[g][0] = make_float2(0.f, 0.f); accI[g][1] = make_float2(0.f, 0.f);
                accH[g][0] = make_float2(0.f, 0.f); accH[g][1] = make_float2(0.f, 0.f);
            }
            float4 pa0 = ldcg4(h0_out + (size_t)(bm0 + lr) * HH + lc);
            float4 pa1 = ldcg4(h1_in  + (size_t)(bm0 + lr) * HH + lc);
            float4 pw[6];
#pragma unroll
            for (int g = 0; g < 3; g++) {
                pw[g]   = *reinterpret_cast<const float4*>(Wih1 + (size_t)(g * HH + jn0 + lr) * HH + lc);
                pw[3+g] = *reinterpret_cast<const float4*>(Whh1 + (size_t)(g * HH + jn0 + lr) * HH + lc);
            }
#pragma unroll 1
            for (int k0 = 0; k0 < HH; k0 += 32) {
                st_tr(SMBUF(0), lc, lr, pa0);
                st_tr(SMBUF(1), lc, lr, pa1);
#pragma unroll
                for (int g = 0; g < 6; g++) st_tr(SMBUF(2 + g), lc, lr, pw[g]);
                __syncthreads();
                if (k0 + 32 < HH) {
                    int kn = k0 + 32;
                    pa0 = ldcg4(h0_out + (size_t)(bm0 + lr) * HH + kn + lc);
                    pa1 = ldcg4(h1_in  + (size_t)(bm0 + lr) * HH + kn + lc);
#pragma unroll
                    for (int g = 0; g < 3; g++) {
                        pw[g]   = *reinterpret_cast<const float4*>(Wih1 + (size_t)(g * HH + jn0 + lr) * HH + kn + lc);
                        pw[3+g] = *reinterpret_cast<const float4*>(Whh1 + (size_t)(g * HH + jn0 + lr) * HH + kn + lc);
                    }
                }
#pragma unroll
                for (int k = 0; k < 32; k++) {
                    float2 xv = lds2(SMBUF(0) + k * TS + 2 * ty);
                    float2 hv = lds2(SMBUF(1) + k * TS + 2 * ty);
                    float2 x0 = bc2(xv.x), x1 = bc2(xv.y);
                    float2 h0b = bc2(hv.x), h1b = bc2(hv.y);
#pragma unroll
                    for (int g = 0; g < 3; g++) {
                        float2 bw = lds2(SMBUF(2 + g) + k * TS + 2 * tx);
                        accI[g][0] = ffma2(x0, bw, accI[g][0]);
                        accI[g][1] = ffma2(x1, bw, accI[g][1]);
                        float2 cw = lds2(SMBUF(5 + g) + k * TS + 2 * tx);
                        accH[g][0] = ffma2(h0b, cw, accH[g][0]);
                        accH[g][1] = ffma2(h1b, cw, accH[g][1]);
                    }
                }
                __syncthreads();
            }
#pragma unroll
            for (int mi = 0; mi < 2; mi++) {
#pragma unroll
                for (int ni = 0; ni < 2; ni++) {
                    int b = bm0 + 2 * ty + mi;
                    int j = jn0 + 2 * tx + ni;
                    float ir  = __fadd_rn(ni ? accI[0][mi].y : accI[0][mi].x, bih1[j]);
                    float iz  = __fadd_rn(ni ? accI[1][mi].y : accI[1][mi].x, bih1[j + HH]);
                    float inn = __fadd_rn(ni ? accI[2][mi].y : accI[2][mi].x, bih1[j + 2 * HH]);
                    float hr  = __fadd_rn(ni ? accH[0][mi].y : accH[0][mi].x, bhh1[j]);
                    float hz  = __fadd_rn(ni ? accH[1][mi].y : accH[1][mi].x, bhh1[j + HH]);
                    float hn  = __fadd_rn(ni ? accH[2][mi].y : accH[2][mi].x, bhh1[j + 2 * HH]);
                    float r  = jax_sigmoid(__fadd_rn(ir, hr));
                    float z  = jax_sigmoid(__fadd_rn(iz, hz));
                    float ng = tanhf(__fadd_rn(inn, __fmul_rn(r, hn)));
                    float hp = __ldcg(&h1_in[(size_t)b * HH + j]);
                    h1_out[(size_t)b * HH + j] =
                        __fadd_rn(__fmul_rn(__fsub_rn(1.0f, z), ng), __fmul_rn(z, hp));
                }
            }
        }
        gsync();

        // ---------------- logits = h1n @ W_out^T + b_out ----------------
        {
            float2 acc[2];
            acc[0] = make_float2(0.f, 0.f); acc[1] = make_float2(0.f, 0.f);
            float4 pa = ldcg4(h1_out + (size_t)(bm0 + lr) * HH + lc);
            float4 pb = *reinterpret_cast<const float4*>(Wout + (size_t)(jn0 + lr) * HH + lc);
#pragma unroll 1
            for (int k0 = 0; k0 < HH; k0 += 32) {
                st_tr(SMBUF(0), lc, lr, pa);
                st_tr(SMBUF(1), lc, lr, pb);
                __syncthreads();
                if (k0 + 32 < HH) {
                    int kn = k0 + 32;
                    pa = ldcg4(h1_out + (size_t)(bm0 + lr) * HH + kn + lc);
                    pb = *reinterpret_cast<const float4*>(Wout + (size_t)(jn0 + lr) * HH + kn + lc);
                }
#pragma unroll
                for (int k = 0; k < 32; k++) {
                    float2 av = lds2(SMBUF(0) + k * TS + 2 * ty);
                    float2 bw = lds2(SMBUF(1) + k * TS + 2 * tx);
                    acc[0] = ffma2(bc2(av.x), bw, acc[0]);
                    acc[1] = ffma2(bc2(av.y), bw, acc[1]);
                }
                __syncthreads();
            }
#pragma unroll
            for (int mi = 0; mi < 2; mi++)
#pragma unroll
                for (int ni = 0; ni < 2; ni++) {
                    int b = bm0 + 2 * ty + mi;
                    int c = jn0 + 2 * tx + ni;
                    g_logits[(size_t)b * NN + c] =
                        __fadd_rn(ni ? acc[mi].y : acc[mi].x, bout[c]);
                }
        }
        gsync();

        // ------- sample: both rows in parallel, shuffle reductions -------
        {
            // smem scratch (post-gsync, safe to reuse)
            float* W_S = SM;                 // [8] per-warp argmax value
            int*   W_I = (int*)(SM + 8);     // [8] per-warp argmax index
            float* W_V = SM + 16;            // [8] per-warp vmax
            float* W_E = SM + 24;            // [8] per-warp expsum
            float* VV  = SM + 64;            // [2][512] masked logits

            const int r    = tid >> 7;       // row within block pair
            const int c0   = tid & 127;
            const int wip  = (tid >> 5) & 3; // warp within row
            const int b    = 2 * blk + r;

            unsigned sk0, sk1;
            tf2x32(0u, 42u, 0u, (unsigned)t, sk0, sk1);   // step key

            float vq[4];
            float bs = -3.4e38f; int bi = 0;
            float lv = -3.4e38f;
#pragma unroll
            for (int q = 0; q < 4; q++) {
                int col = c0 + 128 * q;
                float lg = __ldcg(&g_logits[(size_t)b * NN + col]);
                unsigned w = g_avail[b * (NN / 32) + (col >> 5)];
                float v = ((w >> (col & 31)) & 1u) ? lg : NEG_INF;
                vq[q] = v;
                VV[r * NN + col] = v;
                unsigned o0, o1;
                tf2x32(sk0, sk1, 0u, (unsigned)(b * NN + col), o0, o1);
                unsigned bits = o0 ^ o1;
                float f = __fsub_rn(__uint_as_float((bits >> 9) | 0x3F800000u), 1.0f);
                float gmb = -logf(-logf(fmaxf(f, F32_TINY)));
                float s = __fadd_rn(gmb, v);
                if (s > bs || (s == bs && col < bi)) { bs = s; bi = col; }
                lv = fmaxf(lv, v);
            }
#pragma unroll
            for (int off = 16; off > 0; off >>= 1) {
                float os = __shfl_xor_sync(0xFFFFFFFFu, bs, off);
                int   oi = __shfl_xor_sync(0xFFFFFFFFu, bi, off);
                float ov = __shfl_xor_sync(0xFFFFFFFFu, lv, off);
                if (os > bs || (os == bs && oi < bi)) { bs = os; bi = oi; }
                lv = fmaxf(lv, ov);
            }
            if ((tid & 31) == 0) {
                W_S[r * 4 + wip] = bs; W_I[r * 4 + wip] = bi; W_V[r * 4 + wip] = lv;
            }
            __syncthreads();
            float vmax = W_V[r * 4];
            float fs = W_S[r * 4]; int fi = W_I[r * 4];
#pragma unroll
            for (int w = 1; w < 4; w++) {
                float os = W_S[r * 4 + w]; int oi = W_I[r * 4 + w];
                if (os > fs || (os == fs && oi < fi)) { fs = os; fi = oi; }
                vmax = fmaxf(vmax, W_V[r * 4 + w]);
            }
            // expsum
            float es = 0.0f;
#pragma unroll
            for (int q = 0; q < 4; q++)
                es = __fadd_rn(es, expf(__fsub_rn(vq[q], vmax)));
#pragma unroll
            for (int off = 16; off > 0; off >>= 1)
                es = __fadd_rn(es, __shfl_xor_sync(0xFFFFFFFFu, es, off));
            if ((tid & 31) == 0) W_E[r * 4 + wip] = es;
            __syncthreads();

            if (c0 == 0) {
                float S = __fadd_rn(__fadd_rn(W_E[r * 4], W_E[r * 4 + 1]),
                                    __fadd_rn(W_E[r * 4 + 2], W_E[r * 4 + 3]));
                int idx = fi;
                float ps = __fdiv_rn(expf(__fsub_rn(VV[r * NN + idx], vmax)), S);
                float lp = __fadd_rn(g_lp[b], logf(__fadd_rn(ps, 1e-9f)));
                g_lp[b]  = lp;
                g_sel[b] = idx;
                g_avail[b * (NN / 32) + (idx >> 5)] &= ~(1u << (idx & 31));
                out[(size_t)b * NN * NN + (size_t)t * NN + idx] = 1.0f;
                if (t == NN - 1) out[(size_t)BB * NN * NN + b] = lp;
            }
        }
        gsync();
    }
}

// -------- host launcher: 2 graph nodes (memset + persistent kernel) --------
extern "C" void kernel_launch(void* const* d_in, const int* in_sizes, int n_in,
                              void* d_out, int out_size)
{
    int base = (n_in == 11) ? 1 : 0;   // batch_size scalar first per metadata
    const float* Wih0 = (const float*)d_in[base + 0];
    const float* Whh0 = (const float*)d_in[base + 1];
    const float* bih0 = (const float*)d_in[base + 2];
    const float* bhh0 = (const float*)d_in[base + 3];
    const float* Wih1 = (const float*)d_in[base + 4];
    const float* Whh1 = (const float*)d_in[base + 5];
    const float* bih1 = (const float*)d_in[base + 6];
    const float* bhh1 = (const float*)d_in[base + 7];
    const float* Wout = (const float*)d_in[base + 8];
    const float* bout = (const float*)d_in[base + 9];
    float* out = (float*)d_out;
    (void)in_sizes;

    cudaMemsetAsync(d_out, 0, (size_t)out_size * sizeof(float), 0);
    perm_persistent<<<GBLK, NTHR>>>(Wih0, Whh0, bih0, bhh0,
                                    Wih1, Whh1, bih1, bhh1,
                                    Wout, bout, out);
}